// round 10
// baseline (speedup 1.0000x reference)
#include <cuda_runtime.h>

#define B_   64
#define NI   2048
#define NO   32
#define DDO  16
#define DDI  16
#define OD   512
#define NBLK 148
#define THREADS 1024

typedef unsigned long long ull;

// ---- shared memory (float offsets) ----
#define WT_PITCH 516
#define WT_SZ    (DDI * WT_PITCH)            // 8256
#define S_WT(b)  ((b) * WT_SZ)               // two W buffers
#define S_XD(b)  (16512 + (b) * 2048)        // two x-dup buffers: ull [16][64]
#define S_XP(b)  (20608 + (b) * 1280)        // two compact x rows: [64][20]
#define S_WS     23168                       // Wsum [16][33]
#define S_CT(b)  (23696 + (b) * 2176)        // two c2 buffers [32][68]
#define SMEM_FLOATS 28048                    // 112192 B

#define XCOL(b) ((((b) & 3) << 4) | ((b) >> 2))

// partials: [seg][o][b][d] ; monotone grid-sync ticket
__device__ float    g_part[(size_t)NBLK * OD * B_];
__device__ unsigned g_cnt = 0;

__device__ __forceinline__ void fma2(ull& d, ull a, ull b) {
    asm("fma.rn.f32x2 %0, %1, %2, %0;" : "+l"(d) : "l"(a), "l"(b));
}
__device__ __forceinline__ ull mul2(ull a, ull b) {
    ull r; asm("mul.rn.f32x2 %0, %1, %2;" : "=l"(r) : "l"(a), "l"(b)); return r;
}
__device__ __forceinline__ ull pack_dup(float a) {
    ull r; asm("mov.b64 %0, {%1, %1};" : "=l"(r) : "f"(a)); return r;
}
__device__ __forceinline__ float2 unpk(ull a) {
    float2 r; asm("mov.b64 {%0, %1}, %2;" : "=f"(r.x), "=f"(r.y) : "l"(a)); return r;
}

extern "C" __global__ void __launch_bounds__(THREADS, 1)
capsule_main(const float* __restrict__ X, const float* __restrict__ W,
             float* __restrict__ out)
{
    extern __shared__ float sm[];
    float* sWs = sm + S_WS;

    const int tid  = threadIdx.x;
    const int lane = tid & 31;
    const int wid  = tid >> 5;
    const int o    = wid;                    // contraction: o = warp id (0..31)
    const int dh   = (tid >> 4) & 1;         // d-half (0/1)
    const int bg   = tid & 15;               // batch group: b = 4*bg + j

    // acc[p][j]: f32x2 over od = o*16 + dh*8 + 2p,2p+1 ; batch b = 4*bg + j
    ull acc[4][4];
    #pragma unroll
    for (int p = 0; p < 4; p++)
        #pragma unroll
        for (int j = 0; j < 4; j++) acc[p][j] = 0ull;

    float4 wv0, wv1;                         // W prefetch (8 regs)
    float4 xv;                               // x prefetch (tid<256)

#define LDG_TILE(nn)                                                          \
    {                                                                         \
        const float4* Wg = (const float4*)(W + (size_t)(nn) * (OD * DDI));    \
        wv0 = Wg[tid]; wv1 = Wg[tid + 1024];                                  \
        if (tid < 256)                                                        \
            xv = *(const float4*)(X + ((size_t)(tid >> 2) * NI + (nn)) * DDI  \
                                  + (tid & 3) * 4);                           \
    }

#define STAGE_TILE(bf)                                                        \
    {                                                                         \
        float* wt = sm + S_WT(bf);                                            \
        {                                                                     \
            int g = tid, od = g >> 2, i0 = (g & 3) * 4;                       \
            wt[(i0 + 0) * WT_PITCH + od] = wv0.x;                             \
            wt[(i0 + 1) * WT_PITCH + od] = wv0.y;                             \
            wt[(i0 + 2) * WT_PITCH + od] = wv0.z;                             \
            wt[(i0 + 3) * WT_PITCH + od] = wv0.w;                             \
        }                                                                     \
        {                                                                     \
            int g = tid + 1024, od = g >> 2, i0 = (g & 3) * 4;                \
            wt[(i0 + 0) * WT_PITCH + od] = wv1.x;                             \
            wt[(i0 + 1) * WT_PITCH + od] = wv1.y;                             \
            wt[(i0 + 2) * WT_PITCH + od] = wv1.z;                             \
            wt[(i0 + 3) * WT_PITCH + od] = wv1.w;                             \
        }                                                                     \
        if (tid < 256) {                                                      \
            int b = tid >> 2, i0 = (tid & 3) * 4, bc = XCOL(b);               \
            ull* xd = (ull*)(sm + S_XD(bf));                                  \
            xd[(i0 + 0) * 64 + bc] = pack_dup(xv.x);                          \
            xd[(i0 + 1) * 64 + bc] = pack_dup(xv.y);                          \
            xd[(i0 + 2) * 64 + bc] = pack_dup(xv.z);                          \
            xd[(i0 + 3) * 64 + bc] = pack_dup(xv.w);                          \
            *(float4*)(sm + S_XP(bf) + b * 20 + i0) = xv;                     \
        }                                                                     \
    }

#define WSUM(bf)                                                              \
    if (tid < 512) {                                                          \
        int oo = tid >> 4, ii = tid & 15;                                     \
        const float* r = sm + S_WT(bf) + ii * WT_PITCH + oo * 16;             \
        float4 a = *(const float4*)(r);                                       \
        float4 b = *(const float4*)(r + 4);                                   \
        float4 c = *(const float4*)(r + 8);                                   \
        float4 d = *(const float4*)(r + 12);                                  \
        sWs[ii * 33 + oo] =                                                   \
            ((a.x + a.y) + (a.z + a.w)) + ((b.x + b.y) + (b.z + b.w)) +       \
            ((c.x + c.y) + (c.z + c.w)) + ((d.x + d.y) + (d.z + d.w));        \
    }

#define ROUTE(bf)                                                             \
    {                                                                         \
        float ws[16];                                                         \
        _Pragma("unroll")                                                     \
        for (int i = 0; i < 16; i++) ws[i] = sWs[i * 33 + lane];              \
        float* ct = sm + S_CT(bf);                                            \
        _Pragma("unroll")                                                     \
        for (int bb = 0; bb < 2; bb++) {                                      \
            int b = wid + 32 * bb;                                            \
            const float* xp = sm + S_XP(bf) + b * 20;                         \
            float h = 0.f;                                                    \
            _Pragma("unroll")                                                 \
            for (int q = 0; q < 4; q++) {                                     \
                float4 xq = *(const float4*)(xp + 4 * q);                     \
                h = fmaf(ws[4 * q + 0], xq.x, h);                             \
                h = fmaf(ws[4 * q + 1], xq.y, h);                             \
                h = fmaf(ws[4 * q + 2], xq.z, h);                             \
                h = fmaf(ws[4 * q + 3], xq.w, h);                             \
            }                                                                 \
            float b1 = h * 0.03125f;                                          \
            float e1 = __expf(b1);                                            \
            float s1 = e1;                                                    \
            _Pragma("unroll")                                                 \
            for (int off = 16; off; off >>= 1)                                \
                s1 += __shfl_xor_sync(0xffffffffu, s1, off);                  \
            float b2 = fmaf(__fdividef(e1, s1), h, b1);                       \
            float e2 = __expf(b2);                                            \
            float s2 = e2;                                                    \
            _Pragma("unroll")                                                 \
            for (int off = 16; off; off >>= 1)                                \
                s2 += __shfl_xor_sync(0xffffffffu, s2, off);                  \
            ct[lane * 68 + b] = __fdividef(e2, s2);                           \
        }                                                                     \
    }

    // ---------------- prologue: stage + route n0, prefetch n1 ----------------
    int n = blockIdx.x;
    LDG_TILE(n);
    STAGE_TILE(0);
    __syncthreads();
    WSUM(0);
    if (n + NBLK < NI) LDG_TILE(n + NBLK);
    __syncthreads();
    ROUTE(0);

    int buf = 0;
    for (; n < NI; n += NBLK) {
        __syncthreads();                                   // A
        const bool hn = (n + NBLK) < NI;
        if (hn) STAGE_TILE(buf ^ 1);
        __syncthreads();                                   // B
        if (hn) WSUM(buf ^ 1);
        __syncthreads();                                   // C
        if (hn) ROUTE(buf ^ 1);
        if (n + 2 * NBLK < NI) LDG_TILE(n + 2 * NBLK);     // covered by contraction

        // ---- contraction for n (buffer `buf`) ----
        {
            const float* wt = sm + S_WT(buf) + o * 16 + dh * 8;
            const ull*   xd = (const ull*)(sm + S_XD(buf));
            float4 cv = *(const float4*)(sm + S_CT(buf) + o * 68 + 4 * bg);
            ull c2d[4];
            c2d[0] = pack_dup(cv.x); c2d[1] = pack_dup(cv.y);
            c2d[2] = pack_dup(cv.z); c2d[3] = pack_dup(cv.w);

            #pragma unroll
            for (int i = 0; i < DDI; i++) {
                ulonglong2 w01 = *(const ulonglong2*)(wt + i * WT_PITCH);
                ulonglong2 w23 = *(const ulonglong2*)(wt + i * WT_PITCH + 4);
                const ull* xrow = xd + i * 64 + bg;
                #pragma unroll
                for (int j = 0; j < 4; j++) {
                    ull xs = mul2(xrow[j * 16], c2d[j]);
                    fma2(acc[0][j], w01.x, xs);
                    fma2(acc[1][j], w01.y, xs);
                    fma2(acc[2][j], w23.x, xs);
                    fma2(acc[3][j], w23.y, xs);
                }
            }
        }
        buf ^= 1;
    }

    // ---- writeout partials: g_part[seg][o][b][d] ----
    {
        float* gp = g_part + (size_t)blockIdx.x * (OD * B_) + o * 1024 + dh * 8;
        #pragma unroll
        for (int j = 0; j < 4; j++) {
            float2 a0 = unpk(acc[0][j]);
            float2 a1 = unpk(acc[1][j]);
            float2 a2 = unpk(acc[2][j]);
            float2 a3 = unpk(acc[3][j]);
            float* pj = gp + (4 * bg + j) * 16;
            *(float4*)(pj)     = make_float4(a0.x, a0.y, a1.x, a1.y);
            *(float4*)(pj + 4) = make_float4(a2.x, a2.y, a3.x, a3.y);
        }
    }

    // ---- software grid barrier (monotone ticket; graph-replay safe) ----
    __threadfence();
    __syncthreads();
    if (tid == 0) {
        unsigned t = atomicAdd(&g_cnt, 1u);
        unsigned target = (t / NBLK + 1u) * NBLK;
        while ((int)(*(volatile unsigned*)&g_cnt) - (int)target < 0) {}
        __threadfence();
    }
    __syncthreads();

    // ---- fused reduce + squash: 4 threads per float2-output, 37 segs each ----
    {
        const int g = blockIdx.x * THREADS + tid;
        if (g < 65536) {
            const int e    = g >> 2;
            const int part = g & 3;

            const float2* p = ((const float2*)g_part) + (size_t)part * 16384 + e;
            float sx = 0.f, sy = 0.f;
            #pragma unroll
            for (int k = 0; k < 37; k++) {
                const float2* q = p + (size_t)(4 * k) * 16384;
                float2 v;
                v.x = __ldcg(&q->x); v.y = __ldcg(&q->y);
                sx += v.x; sy += v.y;
            }
            sx += __shfl_xor_sync(0xffffffffu, sx, 1);
            sx += __shfl_xor_sync(0xffffffffu, sx, 2);
            sy += __shfl_xor_sync(0xffffffffu, sy, 1);
            sy += __shfl_xor_sync(0xffffffffu, sy, 2);

            float qv = sx * sx + sy * sy;
            qv += __shfl_xor_sync(0xffffffffu, qv, 4);
            qv += __shfl_xor_sync(0xffffffffu, qv, 8);
            qv += __shfl_xor_sync(0xffffffffu, qv, 16);
            float s2 = qv;

            if (part == 0) {
                float scale = s2 / ((1.f + s2) * sqrtf(s2 + 1e-7f));
                int oo = e >> 9, bb = (e >> 3) & 63, dp = e & 7;
                *(float2*)(out + (size_t)bb * (NO * DDO) + oo * 16 + 2 * dp) =
                    make_float2(scale * sx, scale * sy);
            }
        }
    }
}

extern "C" void kernel_launch(void* const* d_in, const int* in_sizes, int n_in,
                              void* d_out, int out_size)
{
    const float* a = (const float*)d_in[0];
    const float* c = (const float*)d_in[1];
    const float *X, *W;
    if (in_sizes[0] == B_ * NI * DDI) { X = a; W = c; }
    else                              { X = c; W = a; }

    size_t smem = (size_t)SMEM_FLOATS * sizeof(float);
    cudaFuncSetAttribute(capsule_main,
                         cudaFuncAttributeMaxDynamicSharedMemorySize, (int)smem);
    capsule_main<<<NBLK, THREADS, smem>>>(X, W, (float*)d_out);
}

// round 11
// speedup vs baseline: 1.1262x; 1.1262x over previous
#include <cuda_runtime.h>

#define B_   64
#define NI   2048
#define NO   32
#define DDO  16
#define DDI  16
#define OD   512
#define NBLK 148
#define THREADS 256

typedef unsigned long long ull;

// ---- shared memory (float offsets) ----
#define WT_PITCH 644
#define S_WT     0                       // W transposed [i][wcol], 16*644 = 10304
#define S_RAW0   10304                   // raw W tile (natural), 8192
#define S_RAW1   18496                   // raw W tile (natural), 8192
#define XD_PITCH 164
#define S_XD     26688                   // dup (x,x) [i][bcol], 16*164 = 2624
#define S_XP     29312                   // natural x rows [b][20], 1280
#define S_WS     30592                   // Wsum [16][33], 528
#define S_CT     31120                   // c2 [32][68], 2176
#define SMEM_FLOATS 33296                // 133184 B

#define WCOL(od) ((((od) >> 4) * 20) + ((od) & 15))
#define BCOL(b)  ((((b) >> 3) * 20) + (((b) & 7) * 2))

// partials: [seg][o][b][d] ; monotone grid-sync ticket
__device__ float    g_part[(size_t)NBLK * OD * B_];
__device__ unsigned g_cnt = 0;

__device__ __forceinline__ void fma2(ull& d, ull a, ull b) {
    asm("fma.rn.f32x2 %0, %1, %2, %0;" : "+l"(d) : "l"(a), "l"(b));
}
__device__ __forceinline__ ull mul2(ull a, ull b) {
    ull r; asm("mul.rn.f32x2 %0, %1, %2;" : "=l"(r) : "l"(a), "l"(b)); return r;
}
__device__ __forceinline__ ull pack_dup(float a) {
    ull r; asm("mov.b64 %0, {%1, %1};" : "=l"(r) : "f"(a)); return r;
}
__device__ __forceinline__ float2 unpk(ull a) {
    float2 r; asm("mov.b64 {%0, %1}, %2;" : "=f"(r.x), "=f"(r.y) : "l"(a)); return r;
}
__device__ __forceinline__ void cpa16(unsigned dst, const float* src) {
    asm volatile("cp.async.cg.shared.global [%0], [%1], 16;" :: "r"(dst), "l"(src));
}
__device__ __forceinline__ void cpa_commit() { asm volatile("cp.async.commit_group;"); }
__device__ __forceinline__ void cpa_wait0()  { asm volatile("cp.async.wait_group 0;"); }

extern "C" __global__ void __launch_bounds__(THREADS, 1)
capsule_main(const float* __restrict__ X, const float* __restrict__ W,
             float* __restrict__ out)
{
    extern __shared__ float sm[];
    float* sWs = sm + S_WS;
    float* sCT = sm + S_CT;

    const int tid  = threadIdx.x;
    const int lane = tid & 31;
    const int wid  = tid >> 5;
    const int o    = tid >> 3;               // contraction o (0..31)
    const int bg   = tid & 7;                // batch block: b = 8*bg + j
    const int b0   = 8 * bg;
    const unsigned smem_u = (unsigned)__cvta_generic_to_shared(sm);

    // acc[p][j]: f32x2 over od = o*16 + 2p, 2p+1 ; batch b0 + j   (128 regs)
    ull acc[8][8];
    #pragma unroll
    for (int p = 0; p < 8; p++)
        #pragma unroll
        for (int j = 0; j < 8; j++) acc[p][j] = 0ull;

    float4 xv;                               // x prefetch: b = tid>>2, quad = tid&3

#define CPA_W(nn, rawoff)                                                     \
    {                                                                         \
        const float* Wg = W + (size_t)(nn) * (OD * DDI);                      \
        unsigned base = smem_u + 4u * (unsigned)(rawoff);                     \
        _Pragma("unroll")                                                     \
        for (int k = 0; k < 8; k++) {                                         \
            int c = tid + k * THREADS;                                        \
            cpa16(base + 16u * (unsigned)c, Wg + 4 * c);                      \
        }                                                                     \
        cpa_commit();                                                         \
    }

#define LDX(nn)                                                               \
    xv = *(const float4*)(X + ((size_t)(tid >> 2) * NI + (nn)) * DDI          \
                          + (tid & 3) * 4);

#define STAGE(rawoff)                                                         \
    {                                                                         \
        const float4* rw = (const float4*)(sm + (rawoff));                    \
        _Pragma("unroll")                                                     \
        for (int k = 0; k < 8; k++) {                                         \
            int c = tid + k * THREADS;                                        \
            float4 v = rw[c];                                                 \
            int od = c >> 2, i0 = (c & 3) * 4;                                \
            float* w0 = sm + S_WT + WCOL(od);                                 \
            w0[(i0 + 0) * WT_PITCH] = v.x;                                    \
            w0[(i0 + 1) * WT_PITCH] = v.y;                                    \
            w0[(i0 + 2) * WT_PITCH] = v.z;                                    \
            w0[(i0 + 3) * WT_PITCH] = v.w;                                    \
        }                                                                     \
        {                                                                     \
            int b = tid >> 2, i0 = (tid & 3) * 4;                             \
            int bc = BCOL(b);                                                 \
            ull* xdu = (ull*)(sm + S_XD);                                     \
            xdu[((i0 + 0) * XD_PITCH + bc) >> 1] = pack_dup(xv.x);            \
            xdu[((i0 + 1) * XD_PITCH + bc) >> 1] = pack_dup(xv.y);            \
            xdu[((i0 + 2) * XD_PITCH + bc) >> 1] = pack_dup(xv.z);            \
            xdu[((i0 + 3) * XD_PITCH + bc) >> 1] = pack_dup(xv.w);            \
            *(float4*)(sm + S_XP + b * 20 + i0) = xv;                         \
        }                                                                     \
    }

#define WSUM()                                                                \
    {                                                                         \
        _Pragma("unroll")                                                     \
        for (int t = tid; t < 512; t += THREADS) {                            \
            int oo = t >> 4, ii = t & 15;                                     \
            const float* r = sm + S_WT + ii * WT_PITCH + oo * 20;             \
            float4 a = *(const float4*)(r);                                   \
            float4 b = *(const float4*)(r + 4);                               \
            float4 c = *(const float4*)(r + 8);                               \
            float4 d = *(const float4*)(r + 12);                              \
            sWs[ii * 33 + oo] =                                               \
                ((a.x + a.y) + (a.z + a.w)) + ((b.x + b.y) + (b.z + b.w)) +   \
                ((c.x + c.y) + (c.z + c.w)) + ((d.x + d.y) + (d.z + d.w));    \
        }                                                                     \
    }

#define ROUTE()                                                               \
    {                                                                         \
        float ws[16];                                                         \
        _Pragma("unroll")                                                     \
        for (int i = 0; i < 16; i++) ws[i] = sWs[i * 33 + lane];              \
        _Pragma("unroll")                                                     \
        for (int bb = 0; bb < 8; bb++) {                                      \
            int b = wid * 8 + bb;                                             \
            const float* xp = sm + S_XP + b * 20;                             \
            float4 xa = *(const float4*)(xp);                                 \
            float4 xb = *(const float4*)(xp + 4);                             \
            float4 xc = *(const float4*)(xp + 8);                             \
            float4 xd = *(const float4*)(xp + 12);                            \
            float h = 0.f;                                                    \
            h = fmaf(ws[0], xa.x, h);  h = fmaf(ws[1], xa.y, h);              \
            h = fmaf(ws[2], xa.z, h);  h = fmaf(ws[3], xa.w, h);              \
            h = fmaf(ws[4], xb.x, h);  h = fmaf(ws[5], xb.y, h);              \
            h = fmaf(ws[6], xb.z, h);  h = fmaf(ws[7], xb.w, h);              \
            h = fmaf(ws[8], xc.x, h);  h = fmaf(ws[9], xc.y, h);              \
            h = fmaf(ws[10], xc.z, h); h = fmaf(ws[11], xc.w, h);             \
            h = fmaf(ws[12], xd.x, h); h = fmaf(ws[13], xd.y, h);             \
            h = fmaf(ws[14], xd.z, h); h = fmaf(ws[15], xd.w, h);             \
            float b1 = h * 0.03125f;                                          \
            float e1 = __expf(b1);                                            \
            float s1 = e1;                                                    \
            _Pragma("unroll")                                                 \
            for (int off = 16; off; off >>= 1)                                \
                s1 += __shfl_xor_sync(0xffffffffu, s1, off);                  \
            float b2 = fmaf(__fdividef(e1, s1), h, b1);                       \
            float e2 = __expf(b2);                                            \
            float s2 = e2;                                                    \
            _Pragma("unroll")                                                 \
            for (int off = 16; off; off >>= 1)                                \
                s2 += __shfl_xor_sync(0xffffffffu, s2, off);                  \
            sCT[lane * 68 + b] = __fdividef(e2, s2);                          \
        }                                                                     \
    }

    // ---------------- prologue ----------------
    int n = blockIdx.x;
    CPA_W(n, S_RAW0);
    LDX(n);

    int cur = 0;
    for (; n < NI; n += NBLK) {
        cpa_wait0();
        __syncthreads();                     // raw[cur] arrived; prev readers done

        STAGE(cur ? S_RAW1 : S_RAW0);        // transpose W, stage x (dup + natural)
        {
            int n2 = n + NBLK;
            if (n2 < NI) {
                CPA_W(n2, cur ? S_RAW0 : S_RAW1);
                LDX(n2);
            }
        }
        __syncthreads();                     // WT/xd/xp visible
        WSUM();
        __syncthreads();                     // sWs visible
        ROUTE();
        __syncthreads();                     // sCT visible

        // ---- contraction: 16 od x 8 b per thread ----
        {
            float4 cv0 = *(const float4*)(sCT + o * 68 + b0);
            float4 cv1 = *(const float4*)(sCT + o * 68 + b0 + 4);
            ull c2d[8];
            c2d[0] = pack_dup(cv0.x); c2d[1] = pack_dup(cv0.y);
            c2d[2] = pack_dup(cv0.z); c2d[3] = pack_dup(cv0.w);
            c2d[4] = pack_dup(cv1.x); c2d[5] = pack_dup(cv1.y);
            c2d[6] = pack_dup(cv1.z); c2d[7] = pack_dup(cv1.w);

            #pragma unroll
            for (int i = 0; i < DDI; i++) {
                const ulonglong2* xr =
                    (const ulonglong2*)(sm + S_XD + i * XD_PITCH + bg * 20);
                ulonglong2 x0 = xr[0], x1 = xr[1], x2 = xr[2], x3 = xr[3];
                ull xs[8];
                xs[0] = mul2(x0.x, c2d[0]); xs[1] = mul2(x0.y, c2d[1]);
                xs[2] = mul2(x1.x, c2d[2]); xs[3] = mul2(x1.y, c2d[3]);
                xs[4] = mul2(x2.x, c2d[4]); xs[5] = mul2(x2.y, c2d[5]);
                xs[6] = mul2(x3.x, c2d[6]); xs[7] = mul2(x3.y, c2d[7]);

                const ulonglong2* wp =
                    (const ulonglong2*)(sm + S_WT + i * WT_PITCH + o * 20);
                ulonglong2 wA = wp[0], wB = wp[1], wC = wp[2], wD = wp[3];
                #pragma unroll
                for (int j = 0; j < 8; j++) {
                    fma2(acc[0][j], wA.x, xs[j]);
                    fma2(acc[1][j], wA.y, xs[j]);
                    fma2(acc[2][j], wB.x, xs[j]);
                    fma2(acc[3][j], wB.y, xs[j]);
                    fma2(acc[4][j], wC.x, xs[j]);
                    fma2(acc[5][j], wC.y, xs[j]);
                    fma2(acc[6][j], wD.x, xs[j]);
                    fma2(acc[7][j], wD.y, xs[j]);
                }
            }
        }
        cur ^= 1;
    }

    // ---- writeout partials: g_part[seg][o][b][d] ----
    {
        float* gp = g_part + (size_t)blockIdx.x * (OD * B_) + o * 1024;
        #pragma unroll
        for (int j = 0; j < 8; j++) {
            float* pj = gp + (b0 + j) * 16;
            float2 a0 = unpk(acc[0][j]); float2 a1 = unpk(acc[1][j]);
            float2 a2 = unpk(acc[2][j]); float2 a3 = unpk(acc[3][j]);
            float2 a4 = unpk(acc[4][j]); float2 a5 = unpk(acc[5][j]);
            float2 a6 = unpk(acc[6][j]); float2 a7 = unpk(acc[7][j]);
            *(float4*)(pj)      = make_float4(a0.x, a0.y, a1.x, a1.y);
            *(float4*)(pj + 4)  = make_float4(a2.x, a2.y, a3.x, a3.y);
            *(float4*)(pj + 8)  = make_float4(a4.x, a4.y, a5.x, a5.y);
            *(float4*)(pj + 12) = make_float4(a6.x, a6.y, a7.x, a7.y);
        }
    }

    // ---- software grid barrier (monotone ticket; graph-replay safe) ----
    __threadfence();
    __syncthreads();
    if (tid == 0) {
        unsigned t = atomicAdd(&g_cnt, 1u);
        unsigned target = (t / NBLK + 1u) * NBLK;
        while ((int)(*(volatile unsigned*)&g_cnt) - (int)target < 0) {}
        __threadfence();
    }
    __syncthreads();

    // ---- fused reduce + squash: 2 threads per float2-output, 74 segs each ----
    {
        const int g = blockIdx.x * THREADS + tid;      // 0..37887
        if (g < 32768) {
            const int e    = g >> 1;                   // float2 output 0..16383
            const int part = g & 1;

            const float2* p = ((const float2*)g_part) + (size_t)part * 16384 + e;
            float sx = 0.f, sy = 0.f;
            #pragma unroll
            for (int k = 0; k < 74; k++) {             // segs part, part+2, ...
                float2 v = __ldcg(p + (size_t)(2 * k) * 16384);
                sx += v.x; sy += v.y;
            }
            sx += __shfl_xor_sync(0xffffffffu, sx, 1); // combine 2 parts
            sy += __shfl_xor_sync(0xffffffffu, sy, 1);

            float qv = sx * sx + sy * sy;              // sum over 8 dp-groups
            qv += __shfl_xor_sync(0xffffffffu, qv, 2);
            qv += __shfl_xor_sync(0xffffffffu, qv, 4);
            qv += __shfl_xor_sync(0xffffffffu, qv, 8);
            float s2 = qv;

            if (part == 0) {
                float scale = s2 / ((1.f + s2) * sqrtf(s2 + 1e-7f));
                int oo = e >> 9, bb = (e >> 3) & 63, dp = e & 7;
                *(float2*)(out + (size_t)bb * (NO * DDO) + oo * 16 + 2 * dp) =
                    make_float2(scale * sx, scale * sy);
            }
        }
    }
}

extern "C" void kernel_launch(void* const* d_in, const int* in_sizes, int n_in,
                              void* d_out, int out_size)
{
    const float* a = (const float*)d_in[0];
    const float* c = (const float*)d_in[1];
    const float *X, *W;
    if (in_sizes[0] == B_ * NI * DDI) { X = a; W = c; }
    else                              { X = c; W = a; }

    size_t smem = (size_t)SMEM_FLOATS * sizeof(float);
    cudaFuncSetAttribute(capsule_main,
                         cudaFuncAttributeMaxDynamicSharedMemorySize, (int)smem);
    capsule_main<<<NBLK, THREADS, smem>>>(X, W, (float*)d_out);
}